// round 14
// baseline (speedup 1.0000x reference)
#include <cuda_runtime.h>
#include <cstdint>
#include <cstddef>

#define B_PTS 256
#define DIM 128
#define N_BANK 500000
#define N_TILES 3907          /* ceil(500000/128) */
#define GRID_GEMM 148
#define THREADS 512
#define K2E 20.609929155556618f   /* log2(e)/0.07 */
#define PADF 132              /* padded floats per SMEM row (conflict-free frags) */

/* Schraudolph exp2: bitcast<float>((int)(s*K2E*2^23 + (127*2^23 - c))) ~= exp(s/T) */
#define SCHA 172888616.0f     /* K2E * 2^23 */
#define SCHB 1064992447.0f    /* 127*2^23 - 360769 */
#define SCHMAX 2130706432.0f  /* 0x7F000000 */

static __device__ float g_part[GRID_GEMM * 2 * B_PTS];
static __device__ int g_done = 0;

// ---------------- helpers ----------------
__device__ __forceinline__ uint32_t smem_u32(const void* p) {
    uint32_t a;
    asm("{ .reg .u64 t; cvta.to.shared.u64 t, %1; cvt.u32.u64 %0, t; }" : "=r"(a) : "l"(p));
    return a;
}
__device__ __forceinline__ float fast_ex2(float x) {
    float y; asm("ex2.approx.ftz.f32 %0, %1;" : "=f"(y) : "f"(x)); return y;
}
__device__ __forceinline__ float approx_expT(float s) {
    float t = fmaf(s, SCHA, SCHB);
    t = fmaxf(t, 0.0f);
    t = fminf(t, SCHMAX);
    return __int_as_float(__float2int_rn(t));
}
__device__ __forceinline__ void cp_async16(uint32_t dst, const void* src) {
    asm volatile("cp.async.cg.shared.global [%0], [%1], 16;"
                 :: "r"(dst), "l"(src) : "memory");
}
#define CP_COMMIT() asm volatile("cp.async.commit_group;" ::: "memory")
#define CP_WAIT1()  asm volatile("cp.async.wait_group 1;" ::: "memory")
#define GROUP_BAR(id) asm volatile("bar.sync %0, 256;" :: "r"(id) : "memory")

// tf32 mma: D(16x8) += A(16x8) * B(8x8).  A row-major, B col-major.
__device__ __forceinline__ void mma_tf32(float c[4], const uint32_t a[4], const uint32_t b[2]) {
    asm volatile(
        "mma.sync.aligned.m16n8k8.row.col.f32.tf32.tf32.f32 "
        "{%0,%1,%2,%3}, {%4,%5,%6,%7}, {%8,%9}, {%0,%1,%2,%3};"
        : "+f"(c[0]), "+f"(c[1]), "+f"(c[2]), "+f"(c[3])
        : "r"(a[0]), "r"(a[1]), "r"(a[2]), "r"(a[3]), "r"(b[0]), "r"(b[1]));
}

// SMEM: A padded [256][132] (resident) + 4 B stage buffers [32][132]
//       + 16 per-warp transpose patches of 8x34 words.
#define SMEM_A_FLOATS (B_PTS * PADF)
#define SMEM_S_FLOATS (32 * PADF)
#define PATCH_W 34
#define PATCH_FLOATS (8 * PATCH_W)
#define SMEM_TOTAL_BYTES ((SMEM_A_FLOATS + 4 * SMEM_S_FLOATS + 16 * PATCH_FLOATS) * 4)

// Load one 32-row stage (32 rows x 128 floats) with 256 group-threads:
// 1024 16B chunks -> 4 iterations.
__device__ __forceinline__ void load_stage(const float* __restrict__ bank, float* sS,
                                           int baserow, int gtid) {
    #pragma unroll
    for (int it = 0; it < 4; it++) {
        int c = it * 256 + gtid;
        int r = c >> 5;
        int ch = c & 31;
        const float* src = bank + (size_t)(baserow + r) * DIM + ch * 4;
        cp_async16(smem_u32(sS + r * PADF + ch * 4), src);
    }
}

// ---------------- single fused kernel ----------------
// 512 threads = 2 independent 8-warp groups.  Group g owns stages
// s = g, g+2, ...  (stage = 32 bank rows), 2 of the 4 stage buffers, its own
// cp.async stream and named barrier -> the groups' LDS/MMA bursts and
// exp/store bursts interleave instead of convoying.
__global__ void __launch_bounds__(THREADS, 1)
hn_fused_kernel(const float* __restrict__ points, const int* __restrict__ pidx,
                const float* __restrict__ bank, float* __restrict__ out, int off) {
    extern __shared__ float sm[];
    float* sA = sm;
    float* sS = sm + SMEM_A_FLOATS;                 // 4 stage buffers
    float* sTr = sS + 4 * SMEM_S_FLOATS;            // 16 warp patches

    const int tid = threadIdx.x;
    const int bid = blockIdx.x;
    const int wid = tid >> 5;
    const int lane = tid & 31;
    const int grp = lane >> 2;          // 0..7
    const int tg = lane & 3;            // 0..3
    const int group = tid >> 8;         // 0 or 1
    const int gtid = tid & 255;
    const int gw = wid & 7;             // warp-in-group: 32-row M block
    const int mwarp = gw * 32;
    const int barid = group + 1;        // named barrier 1 / 2

    // ---- prologue: normalize points into sA (per-CTA; points is L2-hot) ----
    if (tid < B_PTS) {
        const int row = tid;
        const float4* src = reinterpret_cast<const float4*>(points) + row * 32;
        float ss = 0.0f;
        #pragma unroll 8
        for (int i = 0; i < 32; i++) {
            float4 q = src[i];
            ss += q.x * q.x + q.y * q.y + q.z * q.z + q.w * q.w;
        }
        float inv = rsqrtf(ss);
        float* dst = sA + row * PADF;
        #pragma unroll 8
        for (int i = 0; i < 32; i++) {
            float4 q = src[i];
            uint32_t ux, uy, uz, uw;
            asm("cvt.rna.tf32.f32 %0, %1;" : "=r"(ux) : "f"(q.x * inv));
            asm("cvt.rna.tf32.f32 %0, %1;" : "=r"(uy) : "f"(q.y * inv));
            asm("cvt.rna.tf32.f32 %0, %1;" : "=r"(uz) : "f"(q.z * inv));
            asm("cvt.rna.tf32.f32 %0, %1;" : "=r"(uw) : "f"(q.w * inv));
            dst[i * 4 + 0] = __uint_as_float(ux);
            dst[i * 4 + 1] = __uint_as_float(uy);
            dst[i * 4 + 2] = __uint_as_float(uz);
            dst[i * 4 + 3] = __uint_as_float(uw);
        }
    }
    __syncthreads();                    // sA ready; groups now independent

    const int tiles_cnt = (N_TILES - 1 - bid) / GRID_GEMM + 1;
    const int n_stages = tiles_cnt * 4;
    #define STAGE_BASE(s) ((bid + ((s) >> 2) * GRID_GEMM) * 128 + ((s) & 3) * 32)

    // ---- per-group pipeline prologue: stages group, group+2 ----
    {
        int b0 = STAGE_BASE(group);
        if (b0 < N_BANK) load_stage(bank, sS + (group & 3) * SMEM_S_FLOATS, b0, gtid);
        CP_COMMIT();
        int s1 = group + 2;
        if (s1 < n_stages) {
            int b1 = STAGE_BASE(s1);
            if (b1 < N_BANK) load_stage(bank, sS + (s1 & 3) * SMEM_S_FLOATS, b1, gtid);
        }
        CP_COMMIT();
    }

    // per-thread denominator partials: [mt][hi] -> row mwarp + mt*16 + grp + hi*8
    float accR[2][2] = {{0.f, 0.f}, {0.f, 0.f}};

    float* const patch = sTr + wid * PATCH_FLOATS;
    const uint32_t* Au = reinterpret_cast<const uint32_t*>(sA);

    for (int s = group; s < n_stages; s += 2) {
        CP_WAIT1();
        GROUP_BAR(barid);               // group's stage-s data visible

        const int base = STAGE_BASE(s);
        const int valid = (base < N_BANK);   // valid stages are fully valid (500000%32==0)

        float c[2][4][4];
        if (valid) {
            #pragma unroll
            for (int mt = 0; mt < 2; mt++)
                #pragma unroll
                for (int nt = 0; nt < 4; nt++)
                    #pragma unroll
                    for (int q = 0; q < 4; q++) c[mt][nt][q] = 0.f;

            const uint32_t* Bu =
                reinterpret_cast<const uint32_t*>(sS + (s & 3) * SMEM_S_FLOATS);

            #pragma unroll 4
            for (int kt = 0; kt < 16; kt++) {
                const int k0 = kt * 8 + tg;
                uint32_t a[2][4];
                #pragma unroll
                for (int mt = 0; mt < 2; mt++) {
                    int ab = (mwarp + mt * 16 + grp) * PADF + k0;
                    a[mt][0] = Au[ab];
                    a[mt][1] = Au[ab + 8 * PADF];
                    a[mt][2] = Au[ab + 4];
                    a[mt][3] = Au[ab + 8 * PADF + 4];
                }
                uint32_t b[4][2];
                #pragma unroll
                for (int nt = 0; nt < 4; nt++) {
                    int bi = (nt * 8 + grp) * PADF + k0;
                    b[nt][0] = Bu[bi];
                    b[nt][1] = Bu[bi + 4];
                }
                #pragma unroll
                for (int mt = 0; mt < 2; mt++)
                    #pragma unroll
                    for (int nt = 0; nt < 4; nt++)
                        mma_tf32(c[mt][nt], a[mt], b[nt]);
            }
        }

        GROUP_BAR(barid);               // group done reading buffer (s&3)
        // ---- issue load for stage s+4 into this buffer (overlaps epilogue) ----
        {
            const int s4 = s + 4;
            if (s4 < n_stages) {
                int b4 = STAGE_BASE(s4);
                if (b4 < N_BANK)
                    load_stage(bank, sS + (s4 & 3) * SMEM_S_FLOATS, b4, gtid);
            }
            CP_COMMIT();
        }

        // ---- epilogue: exp-accumulate + coalesced stores via warp transpose ----
        if (valid) {
            #pragma unroll
            for (int mt = 0; mt < 2; mt++) {
                #pragma unroll
                for (int hi = 0; hi < 2; hi++) {
                    #pragma unroll
                    for (int nt = 0; nt < 4; nt++) {
                        float v0 = c[mt][nt][hi * 2 + 0];
                        float v1 = c[mt][nt][hi * 2 + 1];
                        accR[mt][hi] += approx_expT(v0) + approx_expT(v1);
                        *reinterpret_cast<float2*>(patch + grp * PATCH_W + nt * 8 + tg * 2) =
                            make_float2(v0, v1);
                    }
                    __syncwarp();
                    float vals[8];
                    #pragma unroll
                    for (int r = 0; r < 8; r++)
                        vals[r] = patch[r * PATCH_W + lane];
                    const int grow = mwarp + mt * 16 + hi * 8;
                    float* pout = out + off + (size_t)grow * N_BANK + base + lane;
                    #pragma unroll
                    for (int r = 0; r < 8; r++)
                        pout[(size_t)r * N_BANK] = vals[r];
                    __syncwarp();
                }
            }
        }
    }

    // ---- reduce denominator partials across the 4 lanes sharing a row ----
    #pragma unroll
    for (int mt = 0; mt < 2; mt++)
        #pragma unroll
        for (int hi = 0; hi < 2; hi++) {
            float v = accR[mt][hi];
            v += __shfl_xor_sync(0xFFFFFFFFu, v, 1);
            v += __shfl_xor_sync(0xFFFFFFFFu, v, 2);
            if (tg == 0) {
                int row = mwarp + mt * 16 + grp + hi * 8;
                g_part[(bid * 2 + group) * B_PTS + row] = v;
            }
        }

    // ---- last-CTA finalize ----
    __shared__ int s_last, s_is64;
    __shared__ float sh[B_PTS];
    __threadfence();
    __syncthreads();                    // both groups rejoin; g_part stores fenced
    if (tid == 0) s_last = (atomicAdd(&g_done, 1) == GRID_GEMM - 1);
    __syncthreads();
    if (!s_last) return;
    __threadfence();

    if (tid == 0) {
        int z = 1;
        for (int i = 1; i < 2 * B_PTS; i += 2)
            if (pidx[i] != 0) { z = 0; break; }
        s_is64 = z;
    }
    __syncthreads();

    if (tid < B_PTS) {
        const int b = tid;
        long long idx = s_is64 ? ((const long long*)pidx)[b] : (long long)pidx[b];
        float d = 0.0f;
        for (int c = 0; c < 2 * GRID_GEMM; c++) d += g_part[c * B_PTS + b];

        // exact fp32 positive similarity: dot(normalize(points[b]), bank[idx])
        const float4* pp = reinterpret_cast<const float4*>(points) + b * 32;
        const float4* bb = reinterpret_cast<const float4*>(bank) + (size_t)idx * 32;
        float ss = 0.0f, dp = 0.0f;
        #pragma unroll 8
        for (int i = 0; i < 32; i++) {
            float4 q = pp[i]; float4 r = bb[i];
            ss += q.x * q.x + q.y * q.y + q.z * q.z + q.w * q.w;
            dp += q.x * r.x + q.y * r.y + q.z * r.z + q.w * r.w;
        }
        float sim = dp * rsqrtf(ss);
        float pos = fast_ex2(sim * K2E);
        sh[b] = -logf(pos / d + 1e-7f);
    }
    __syncthreads();
    for (int o = 128; o > 0; o >>= 1) {
        if (tid < o) sh[tid] += sh[tid + o];
        __syncthreads();
    }
    if (tid == 0) {
        if (off) out[0] = sh[0] * (1.0f / 256.0f);
        g_done = 0;   // reset for next (graph-replayed) call: deterministic
    }
}

// ---------------- launch ----------------
extern "C" void kernel_launch(void* const* d_in, const int* in_sizes, int n_in,
                              void* d_out, int out_size) {
    const float* points = (const float*)d_in[0];
    const int* pidx = (const int*)d_in[1];
    const float* bank = (const float*)d_in[2];
    float* out = (float*)d_out;

    int off = (out_size > 128000000) ? 1 : 0;   // loss scalar precedes sims

    cudaFuncSetAttribute(hn_fused_kernel, cudaFuncAttributeMaxDynamicSharedMemorySize,
                         SMEM_TOTAL_BYTES);

    hn_fused_kernel<<<GRID_GEMM, THREADS, SMEM_TOTAL_BYTES>>>(points, pidx, bank, out, off);
}

// round 15
// speedup vs baseline: 1.5215x; 1.5215x over previous
#include <cuda_runtime.h>
#include <cstdint>
#include <cstddef>

#define B_PTS 256
#define DIM 128
#define N_BANK 500000
#define N_HALVES 7813         /* ceil(500000/64) */
#define GRID_GEMM 148
#define THREADS 512
#define K2E 20.609929155556618f   /* log2(e)/0.07 */
#define PADF_A 136            /* A row stride (words): conflict-free LDS.64 pairs */
#define PADF_B 132            /* B row stride (words): conflict-free LDS.32 frags */

/* Schraudolph exp2: bitcast<float>((int)(s*K2E*2^23 + (127*2^23 - c))) ~= exp(s/T) */
#define SCHA 172888616.0f     /* K2E * 2^23 */
#define SCHB 1064992447.0f    /* 127*2^23 - 360769 */
#define SCHMAX 2130706432.0f  /* 0x7F000000 */

static __device__ float g_part[GRID_GEMM * 2 * B_PTS];
static __device__ int g_done = 0;

// ---------------- helpers ----------------
__device__ __forceinline__ uint32_t smem_u32(const void* p) {
    uint32_t a;
    asm("{ .reg .u64 t; cvta.to.shared.u64 t, %1; cvt.u32.u64 %0, t; }" : "=r"(a) : "l"(p));
    return a;
}
__device__ __forceinline__ float fast_ex2(float x) {
    float y; asm("ex2.approx.ftz.f32 %0, %1;" : "=f"(y) : "f"(x)); return y;
}
__device__ __forceinline__ float approx_expT(float s) {
    float t = fmaf(s, SCHA, SCHB);
    t = fmaxf(t, 0.0f);
    t = fminf(t, SCHMAX);
    return __int_as_float(__float2int_rn(t));
}
__device__ __forceinline__ void cp_async16(uint32_t dst, const void* src, int sz) {
    asm volatile("cp.async.cg.shared.global [%0], [%1], 16, %2;"
                 :: "r"(dst), "l"(src), "r"(sz) : "memory");
}
#define CP_COMMIT() asm volatile("cp.async.commit_group;" ::: "memory")
#define CP_WAIT1()  asm volatile("cp.async.wait_group 1;" ::: "memory")

// tf32 mma: D(16x8) += A(16x8) * B(8x8).  A row-major, B col-major.
__device__ __forceinline__ void mma_tf32(float c[4], const uint32_t a[4], const uint32_t b[2]) {
    asm volatile(
        "mma.sync.aligned.m16n8k8.row.col.f32.tf32.tf32.f32 "
        "{%0,%1,%2,%3}, {%4,%5,%6,%7}, {%8,%9}, {%0,%1,%2,%3};"
        : "+f"(c[0]), "+f"(c[1]), "+f"(c[2]), "+f"(c[3])
        : "r"(a[0]), "r"(a[1]), "r"(a[2]), "r"(a[3]), "r"(b[0]), "r"(b[1]));
}

// SMEM: A permuted [256][136] (resident), two B half-buffers [64][132],
// then 16 per-warp transpose patches of 8x34 words.
#define SMEM_A_FLOATS (B_PTS * PADF_A)        /* 34816 */
#define SMEM_B_FLOATS (64 * PADF_B)           /* 8448 */
#define PATCH_W 34
#define PATCH_FLOATS (8 * PATCH_W)            /* 272 words per warp */
#define SMEM_TOTAL_BYTES ((SMEM_A_FLOATS + 2 * SMEM_B_FLOATS + 16 * PATCH_FLOATS) * 4) /* 224256 */

__device__ __forceinline__ void load_half(const float* __restrict__ bank, float* sBh,
                                          int baserow, int tid) {
    // 2048 16B chunks (64 rows x 32 chunks), 512 threads -> 4 iterations.
    #pragma unroll
    for (int it = 0; it < 4; it++) {
        int c = it * THREADS + tid;
        int r = c >> 5;
        int ch = c & 31;
        int grow = baserow + r;
        int ok = (grow < N_BANK);
        const float* src = bank + (size_t)(ok ? grow : 0) * DIM + ch * 4;
        uint32_t dst = smem_u32(sBh + r * PADF_B + ch * 4);
        cp_async16(dst, src, ok ? 16 : 0);
    }
}

// A column permutation: within each 8-col block store order [0,4,1,5,2,6,3,7]
// so fragment pairs (k, k+4) are adjacent -> LDS.64.
__device__ __forceinline__ int a_perm(int c) {
    return (c & ~7) + ((c & 3) << 1) + ((c >> 2) & 1);
}

// ---------------- single fused kernel ----------------
__global__ void __launch_bounds__(THREADS, 1)
hn_fused_kernel(const float* __restrict__ points, const int* __restrict__ pidx,
                const float* __restrict__ bank, float* __restrict__ out, int off) {
    extern __shared__ float sm[];
    float* sA = sm;
    float* sB0 = sm + SMEM_A_FLOATS;
    float* sB1 = sB0 + SMEM_B_FLOATS;
    float* sTr = sB1 + SMEM_B_FLOATS;   // 16 warp patches

    const int tid = threadIdx.x;
    const int bid = blockIdx.x;
    const int wid = tid >> 5;
    const int lane = tid & 31;
    const int grp = lane >> 2;          // 0..7
    const int tg = lane & 3;            // 0..3
    const int mq = wid & 7;             // which 32-row block of points
    const int nh = wid >> 3;            // which 32-col half of the 64-col B buffer
    const int mwarp = mq * 32;

    // ---- prologue: normalize points into sA (permuted layout) ----
    if (tid < B_PTS) {
        const int row = tid;
        const float4* src = reinterpret_cast<const float4*>(points) + row * 32;
        float ss = 0.0f;
        #pragma unroll 8
        for (int i = 0; i < 32; i++) {
            float4 q = src[i];
            ss += q.x * q.x + q.y * q.y + q.z * q.z + q.w * q.w;
        }
        float inv = rsqrtf(ss);
        float* dst = sA + row * PADF_A;
        #pragma unroll 8
        for (int i = 0; i < 32; i++) {
            float4 q = src[i];
            uint32_t ux, uy, uz, uw;
            asm("cvt.rna.tf32.f32 %0, %1;" : "=r"(ux) : "f"(q.x * inv));
            asm("cvt.rna.tf32.f32 %0, %1;" : "=r"(uy) : "f"(q.y * inv));
            asm("cvt.rna.tf32.f32 %0, %1;" : "=r"(uz) : "f"(q.z * inv));
            asm("cvt.rna.tf32.f32 %0, %1;" : "=r"(uw) : "f"(q.w * inv));
            dst[a_perm(i * 4 + 0)] = __uint_as_float(ux);
            dst[a_perm(i * 4 + 1)] = __uint_as_float(uy);
            dst[a_perm(i * 4 + 2)] = __uint_as_float(uz);
            dst[a_perm(i * 4 + 3)] = __uint_as_float(uw);
        }
    }

    // ---- B pipeline prologue (half-granular striping: half h = bid + g*GRID) ----
    load_half(bank, sB0, bid * 64, tid);
    CP_COMMIT();
    {
        int h1 = bid + GRID_GEMM;
        if (h1 < N_HALVES) load_half(bank, sB1, h1 * 64, tid);
        CP_COMMIT();
    }

    const int n_h = (N_HALVES - 1 - bid) / GRID_GEMM + 1;   // halves this CTA owns

    // per-thread denominator partials: [mt][hi] -> row mwarp + mt*16 + grp + hi*8
    float accR[2][2] = {{0.f, 0.f}, {0.f, 0.f}};

    float* const patch = sTr + wid * PATCH_FLOATS;
    const uint2* Au2 = reinterpret_cast<const uint2*>(sA);

    for (int g = 0; g < n_h; g++) {
        const int buf = g & 1;
        float* Bb = buf ? sB1 : sB0;
        CP_WAIT1();
        __syncthreads();

        const int h = bid + g * GRID_GEMM;
        const int gnb = h * 64;                    // global n base of this half
        int nv = N_BANK - gnb; if (nv > 64) nv = 64;   // 64 or 32 (tail)

        float c[2][4][4];
        {
            #pragma unroll
            for (int mt = 0; mt < 2; mt++)
                #pragma unroll
                for (int nt = 0; nt < 4; nt++)
                    #pragma unroll
                    for (int q = 0; q < 4; q++) c[mt][nt][q] = 0.f;

            const uint32_t* Bu = reinterpret_cast<const uint32_t*>(Bb);

            #pragma unroll 4
            for (int kt = 0; kt < 16; kt++) {
                // A fragments via LDS.64 from permuted layout:
                // uint2 index = (row*136 + kt*8 + 2*tg)/2 = row*68 + kt*4 + tg
                uint32_t a[2][4];
                #pragma unroll
                for (int mt = 0; mt < 2; mt++) {
                    int ai = (mwarp + mt * 16 + grp) * (PADF_A / 2) + kt * 4 + tg;
                    uint2 p0 = Au2[ai];                 // (k0, k0+4)
                    uint2 p1 = Au2[ai + 8 * (PADF_A / 2)];  // rows +8
                    a[mt][0] = p0.x;
                    a[mt][2] = p0.y;
                    a[mt][1] = p1.x;
                    a[mt][3] = p1.y;
                }
                const int k0 = kt * 8 + tg;
                uint32_t b[4][2];
                #pragma unroll
                for (int nt = 0; nt < 4; nt++) {
                    int bi = (nh * 32 + nt * 8 + grp) * PADF_B + k0;
                    b[nt][0] = Bu[bi];
                    b[nt][1] = Bu[bi + 4];
                }
                #pragma unroll
                for (int mt = 0; mt < 2; mt++)
                    #pragma unroll
                    for (int nt = 0; nt < 4; nt++)
                        mma_tf32(c[mt][nt], a[mt], b[nt]);
            }
        }

        __syncthreads();   // all warps done reading buffer g
        // ---- issue load for half g+2 into this buffer (overlaps epilogue) ----
        {
            const int h2 = bid + (g + 2) * GRID_GEMM;
            if (h2 < N_HALVES)
                load_half(bank, (g & 1) ? sB1 : sB0, h2 * 64, tid);
            CP_COMMIT();
        }

        // ---- epilogue: exp-accumulate + coalesced stores via warp transpose ----
        if (nh * 32 < nv) {               // nv in {32,64}: whole 32-col slice valid
            #pragma unroll
            for (int mt = 0; mt < 2; mt++) {
                #pragma unroll
                for (int hi = 0; hi < 2; hi++) {
                    #pragma unroll
                    for (int nt = 0; nt < 4; nt++) {
                        float v0 = c[mt][nt][hi * 2 + 0];
                        float v1 = c[mt][nt][hi * 2 + 1];
                        accR[mt][hi] += approx_expT(v0) + approx_expT(v1);
                        *reinterpret_cast<float2*>(patch + grp * PATCH_W + nt * 8 + tg * 2) =
                            make_float2(v0, v1);
                    }
                    __syncwarp();
                    float vals[8];
                    #pragma unroll
                    for (int r = 0; r < 8; r++)
                        vals[r] = patch[r * PATCH_W + lane];
                    const int grow = mwarp + mt * 16 + hi * 8;
                    float* pout = out + off + (size_t)grow * N_BANK + gnb + nh * 32 + lane;
                    #pragma unroll
                    for (int r = 0; r < 8; r++)
                        pout[(size_t)r * N_BANK] = vals[r];
                    __syncwarp();
                }
            }
        }
    }

    // ---- reduce denominator partials across the 4 lanes sharing a row ----
    #pragma unroll
    for (int mt = 0; mt < 2; mt++)
        #pragma unroll
        for (int hi = 0; hi < 2; hi++) {
            float v = accR[mt][hi];
            v += __shfl_xor_sync(0xFFFFFFFFu, v, 1);
            v += __shfl_xor_sync(0xFFFFFFFFu, v, 2);
            if (tg == 0) {
                int row = mwarp + mt * 16 + grp + hi * 8;
                g_part[(bid * 2 + nh) * B_PTS + row] = v;
            }
        }

    // ---- last-CTA finalize ----
    __shared__ int s_last, s_is64;
    __shared__ float sh[B_PTS];
    __threadfence();
    __syncthreads();                    // all warps' g_part stores done + fenced
    if (tid == 0) s_last = (atomicAdd(&g_done, 1) == GRID_GEMM - 1);
    __syncthreads();
    if (!s_last) return;
    __threadfence();

    if (tid == 0) {
        int z = 1;
        for (int i = 1; i < 2 * B_PTS; i += 2)
            if (pidx[i] != 0) { z = 0; break; }
        s_is64 = z;
    }
    __syncthreads();

    if (tid < B_PTS) {
        const int b = tid;
        long long idx = s_is64 ? ((const long long*)pidx)[b] : (long long)pidx[b];
        float d = 0.0f;
        for (int c = 0; c < 2 * GRID_GEMM; c++) d += g_part[c * B_PTS + b];

        // exact fp32 positive similarity: dot(normalize(points[b]), bank[idx])
        const float4* pp = reinterpret_cast<const float4*>(points) + b * 32;
        const float4* bb = reinterpret_cast<const float4*>(bank) + (size_t)idx * 32;
        float ss = 0.0f, dp = 0.0f;
        #pragma unroll 8
        for (int i = 0; i < 32; i++) {
            float4 q = pp[i]; float4 r = bb[i];
            ss += q.x * q.x + q.y * q.y + q.z * q.z + q.w * q.w;
            dp += q.x * r.x + q.y * r.y + q.z * r.z + q.w * r.w;
        }
        float sim = dp * rsqrtf(ss);
        float pos = fast_ex2(sim * K2E);
        sh[b] = -logf(pos / d + 1e-7f);
    }
    __syncthreads();
    for (int o = 128; o > 0; o >>= 1) {
        if (tid < o) sh[tid] += sh[tid + o];
        __syncthreads();
    }
    if (tid == 0) {
        if (off) out[0] = sh[0] * (1.0f / 256.0f);
        g_done = 0;   // reset for next (graph-replayed) call: deterministic
    }
}

// ---------------- launch ----------------
extern "C" void kernel_launch(void* const* d_in, const int* in_sizes, int n_in,
                              void* d_out, int out_size) {
    const float* points = (const float*)d_in[0];
    const int* pidx = (const int*)d_in[1];
    const float* bank = (const float*)d_in[2];
    float* out = (float*)d_out;

    int off = (out_size > 128000000) ? 1 : 0;   // loss scalar precedes sims

    cudaFuncSetAttribute(hn_fused_kernel, cudaFuncAttributeMaxDynamicSharedMemorySize,
                         SMEM_TOTAL_BYTES);

    hn_fused_kernel<<<GRID_GEMM, THREADS, SMEM_TOTAL_BYTES>>>(points, pidx, bank, out, off);
}